// round 4
// baseline (speedup 1.0000x reference)
#include <cuda_runtime.h>
#include <math.h>

#define NX 160
#define D  48
#define NW 3
#define N3 (NX*NX*NX)
#define M_TV 159

// Scratch (device globals: allocation-free per harness rules)
__device__ float g_G1[NW*NX*D*D];     // [w][a][q][r]
__device__ float g_G2[NW*NX*NX*D];    // [w][a][b][r]
__device__ float g_G3[(size_t)N3*3];  // interleaved: [n = a*160*160+b*160+c][w]
__device__ double g_tv;

__global__ void k_zero() { g_tv = 0.0; }

// K1: G1[w][a][q][r] = sum_p x[a,p] * W[w,p,q,r]
// grid = 3*160 blocks (w*NX+a), 256 threads; each thread 9 contiguous qr outputs
__global__ void k1(const float* __restrict__ x, const float* __restrict__ W) {
    int blk = blockIdx.x;
    int w = blk / NX, a = blk % NX;
    __shared__ float xs[D];
    int t = threadIdx.x;
    if (t < D) xs[t] = x[a*D + t];
    __syncthreads();
    const float* Wp = W + (size_t)w*D*D*D;  // [p][q*48+r]
    float acc[9];
    #pragma unroll
    for (int j = 0; j < 9; j++) acc[j] = 0.f;
    for (int p = 0; p < D; p++) {
        float xv = xs[p];
        const float* row = Wp + p*(D*D);
        #pragma unroll
        for (int j = 0; j < 9; j++) acc[j] = fmaf(xv, row[t + 256*j], acc[j]);
    }
    float* outp = g_G1 + (size_t)blk*(D*D);
    #pragma unroll
    for (int j = 0; j < 9; j++) outp[t + 256*j] = acc[j];
}

// K2: G2[w][a][b][r] = sum_q y[b,q] * G1[w][a][q][r]
// grid = 480 blocks (w*NX+a); 256 threads as (16,16); thread tile 10(b) x 3(r)
__global__ void k2(const float* __restrict__ y) {
    int blk = blockIdx.x;
    __shared__ float ys[NX][D];    // 30720 B (broadcast access, no pad needed)
    __shared__ float g1s[D][D];    // 9216 B (row-contiguous access)
    int t = threadIdx.x;
    const float* G1p = g_G1 + (size_t)blk*D*D;
    for (int i = t; i < NX*D; i += 256) ys[i/D][i%D] = y[i];
    for (int i = t; i < D*D; i += 256) g1s[i/D][i%D] = G1p[i];
    __syncthreads();
    int tx = t & 15, ty = t >> 4;
    float acc[10][3];
    #pragma unroll
    for (int jb = 0; jb < 10; jb++)
        #pragma unroll
        for (int jr = 0; jr < 3; jr++) acc[jb][jr] = 0.f;
    for (int q = 0; q < D; q++) {
        float yv[10], gv[3];
        #pragma unroll
        for (int jb = 0; jb < 10; jb++) yv[jb] = ys[ty + 16*jb][q];
        #pragma unroll
        for (int jr = 0; jr < 3; jr++) gv[jr] = g1s[q][tx + 16*jr];
        #pragma unroll
        for (int jb = 0; jb < 10; jb++)
            #pragma unroll
            for (int jr = 0; jr < 3; jr++)
                acc[jb][jr] = fmaf(yv[jb], gv[jr], acc[jb][jr]);
    }
    float* outp = g_G2 + (size_t)blk*NX*D;
    #pragma unroll
    for (int jb = 0; jb < 10; jb++)
        #pragma unroll
        for (int jr = 0; jr < 3; jr++)
            outp[(ty + 16*jb)*D + tx + 16*jr] = acc[jb][jr];
}

// K3: g[w,a,b,c] = sum_r G2[w][a][b][r] * z[c,r], stored interleaved g_G3[n*3+w]
// grid = 960 blocks: ((w*NX+a)*2 + half); 256 threads (16,16); tile 5(b) x 10(c)
__global__ void k3(const float* __restrict__ z) {
    int blk = blockIdx.x;
    int half = blk & 1;
    int wa = blk >> 1;
    int w = wa / NX, a = wa % NX;
    __shared__ float zs[NX][D + 1];   // pad: lane-stride-48 access would conflict
    __shared__ float g2s[80][D];      // broadcast access, no pad
    int t = threadIdx.x;
    for (int i = t; i < NX*D; i += 256) zs[i/D][i%D] = z[i];
    const float* G2p = g_G2 + ((size_t)wa*NX + half*80)*D;
    for (int i = t; i < 80*D; i += 256) g2s[i/D][i%D] = G2p[i];
    __syncthreads();
    int tx = t & 15, ty = t >> 4;
    float acc[5][10];
    #pragma unroll
    for (int jb = 0; jb < 5; jb++)
        #pragma unroll
        for (int jc = 0; jc < 10; jc++) acc[jb][jc] = 0.f;
    for (int r = 0; r < D; r++) {
        float gv[5], zv[10];
        #pragma unroll
        for (int jb = 0; jb < 5; jb++) gv[jb] = g2s[ty + 16*jb][r];
        #pragma unroll
        for (int jc = 0; jc < 10; jc++) zv[jc] = zs[tx + 16*jc][r];
        #pragma unroll
        for (int jb = 0; jb < 5; jb++)
            #pragma unroll
            for (int jc = 0; jc < 10; jc++)
                acc[jb][jc] = fmaf(gv[jb], zv[jc], acc[jb][jc]);
    }
    int b0 = half*80;
    #pragma unroll
    for (int jb = 0; jb < 5; jb++) {
        int b = b0 + ty + 16*jb;
        size_t rowbase = ((size_t)(a*NX + b))*NX;
        #pragma unroll
        for (int jc = 0; jc < 10; jc++) {
            int c = tx + 16*jc;
            g_G3[(rowbase + c)*3 + w] = acc[jb][jc];
        }
    }
}

// TV: sum over w,a,b,c<159 of sqrt(eps + dc^2 + db^2 + da^2)
__global__ void k_tv() {
    int idx = blockIdx.x*blockDim.x + threadIdx.x;
    float val = 0.f;
    const int M = M_TV;
    if (idx < M*M*M) {
        int c = idx % M;
        int tmp = idx / M;
        int b = tmp % M;
        int a = tmp / M;
        size_t p = ((size_t)(a*NX + b)*NX + c)*3;
        #pragma unroll
        for (int w = 0; w < 3; w++) {
            float v0 = g_G3[p + w];
            float dc = g_G3[p + 3 + w] - v0;              // c+1
            float db = g_G3[p + NX*3 + w] - v0;           // b+1
            float da = g_G3[p + (size_t)NX*NX*3 + w] - v0; // a+1
            val += sqrtf(1e-5f + dc*dc + db*db + da*da);
        }
    }
    // block reduction
    #pragma unroll
    for (int o = 16; o > 0; o >>= 1) val += __shfl_down_sync(0xffffffffu, val, o);
    __shared__ float warp_sums[8];
    int t = threadIdx.x;
    if ((t & 31) == 0) warp_sums[t >> 5] = val;
    __syncthreads();
    if (t == 0) {
        float s = 0.f;
        #pragma unroll
        for (int i = 0; i < 8; i++) s += warp_sums[i];
        atomicAdd(&g_tv, (double)s);
    }
}

__global__ void k_fin(float* __restrict__ out, int pos) {
    double denom = (double)M_TV * M_TV * M_TV;
    out[pos] = (float)(g_tv / denom);  // SCALING = 1.0
}

// Gather: out[i][w] = sum_k B_w[i,k] * g3[B_idx[i,k]][w]
__global__ void k_gather(const int* __restrict__ B_idx, const float* __restrict__ B_w,
                         float* __restrict__ out, int NP) {
    int i = blockIdx.x*blockDim.x + threadIdx.x;
    if (i >= NP) return;
    const int4*   bi = (const int4*)(B_idx + (size_t)i*8);
    const float4* bw = (const float4*)(B_w + (size_t)i*8);
    int4 i0 = bi[0], i1 = bi[1];
    float4 w0 = bw[0], w1 = bw[1];
    int   idxs[8] = {i0.x, i0.y, i0.z, i0.w, i1.x, i1.y, i1.z, i1.w};
    float ws[8]   = {w0.x, w0.y, w0.z, w0.w, w1.x, w1.y, w1.z, w1.w};
    float a0 = 0.f, a1 = 0.f, a2 = 0.f;
    #pragma unroll
    for (int k = 0; k < 8; k++) {
        const float* p = g_G3 + (size_t)idxs[k]*3;
        float wk = ws[k];
        a0 = fmaf(wk, __ldg(p + 0), a0);
        a1 = fmaf(wk, __ldg(p + 1), a1);
        a2 = fmaf(wk, __ldg(p + 2), a2);
    }
    size_t o = (size_t)i*3;
    out[o + 0] = a0;
    out[o + 1] = a1;
    out[o + 2] = a2;
}

extern "C" void kernel_launch(void* const* d_in, const int* in_sizes, int n_in,
                              void* d_out, int out_size) {
    const float* x  = (const float*)d_in[0];
    const float* y  = (const float*)d_in[1];
    const float* z  = (const float*)d_in[2];
    const float* W  = (const float*)d_in[3];
    const int*   Bi = (const int*)d_in[4];
    const float* Bw = (const float*)d_in[5];
    float* out = (float*)d_out;
    int NP = in_sizes[4] / 8;

    k_zero<<<1, 1>>>();
    k1<<<NW*NX, 256>>>(x, W);
    k2<<<NW*NX, 256>>>(y);
    k3<<<NW*NX*2, 256>>>(z);
    int tvN = M_TV*M_TV*M_TV;
    k_tv<<<(tvN + 255)/256, 256>>>();
    k_gather<<<(NP + 255)/256, 256>>>(Bi, Bw, out, NP);
    k_fin<<<1, 1>>>(out, out_size - 1);
}